// round 15
// baseline (speedup 1.0000x reference)
#include <cuda_runtime.h>
#include <cuda_fp16.h>
#include <cstdint>

// Problem constants
#define BB     64
#define CC     20
#define NAA    5
#define HHH    19
#define WWW    19
#define HW     361      // 19*19
#define TT     50
#define NBB    1280     // B*C
#define A4     1805     // NA*H*W
#define CHN    30       // NA*(5+NCPA)
#define EPS12  1e-12f
#define RB     4                              // rows per band
#define BANDS  5
#define TILE   (NAA * RB * WWW)               // 380 cells per band-block
#define TPB    96                             // 3 warps; 4 cells/thread
#define MAIN_BLOCKS (NBB * BANDS)             // 6400
#define CLS_N   (BB * A4)                     // 115520
#define CLS_BLOCKS ((CLS_N + TPB - 1) / TPB)  // 1204
#define TOTB    (MAIN_BLOCKS + CLS_BLOCKS)
#define DONE_PER_B (CC * BANDS)               // 100 main blocks per batch

// Static scratch (no allocations; self-cleaning across graph replays)
__device__ int    g_cnt[CLS_N];               // winners per (b, a4) across C
__device__ float  g_tsum[CLS_N];
__device__ unsigned int g_bdone[BB];          // main blocks finished per batch
__device__ float  g_accf[3];                  // dense, cls nll, nsel
__device__ unsigned int g_done;

struct alignas(16) GTH { __half2 gl, gr, gt, gb; };

__device__ __forceinline__ float fsigm(float v) {
    return __fdividef(1.0f, 1.0f + __expf(-v));
}

// ---------------------------------------------------------------------------
// ONE kernel. Main blocks [0, MAIN_BLOCKS): recompute their nb's target
// assignment in shared (redundantly, 5x per nb — cheaper than a separate
// latency-bound launch), then do the dense losses with the packed-fp16 cull
// loop. Cls blocks [MAIN_BLOCKS, TOTB): spin until their batch's 100 main
// blocks published g_cnt/g_tsum, then compute the NLL. Deadlock-free: cls
// indices strictly follow main indices, mains never wait.
__global__ void __launch_bounds__(TPB, 9)
k_all(const float* __restrict__ out,
      const float* __restrict__ target,
      const float* __restrict__ anchors,
      float* __restrict__ res) {
    int tid = threadIdx.x;

    if (blockIdx.x < MAIN_BLOCKS) {
        int nb   = blockIdx.x / BANDS;
        int band = blockIdx.x - nb * BANDS;
        int h0   = band * RB;
        int b    = nb / CC;

        // ---- shared state ----
        __shared__ float   s_tg[TT * 5];
        __shared__ int     s_ng, s_m, s_nasg;
        __shared__ int     s_cellAll[TT];      // cells of ALL targets (dedupe)
        __shared__ GTH     s_gh[TT];
        __shared__ __half2 s_gcn2[TT];
        __shared__ int     s_cell[TT];         // assigned cells in THIS band
        __shared__ float   s_val[TT][5];
        __shared__ uint32_t s_bits[57];

        if (tid == 0) { s_ng = TT; s_m = 0; s_nasg = 0; }
        if (tid < 57) s_bits[tid] = 0u;
        const float* tg = target + (size_t)nb * TT * 5;
        for (int i = tid; i < TT * 5; i += TPB) s_tg[i] = tg[i];
        __syncthreads();

        if (tid < TT && s_tg[tid * 5 + 1] == 0.0f) atomicMin(&s_ng, tid);
        __syncthreads();
        int ng = s_ng;

        // ---- per-target: box, best anchor, cell, band filter ----
        float gx = 0.f, gy = 0.f, gw = 0.f, gh = 0.f, ct = 0.f;
        int gi = 0, gj = 0, bn = 0, cell = -1;
        float awb = 1.f, ahb = 1.f;
        if (tid < ng) {
            ct = s_tg[tid * 5 + 0];
            gx = s_tg[tid * 5 + 1] * (float)WWW;
            gy = s_tg[tid * 5 + 2] * (float)HHH;
            gw = s_tg[tid * 5 + 3] * (float)WWW;
            gh = s_tg[tid * 5 + 4] * (float)HHH;

            float best = -1.0f;
#pragma unroll
            for (int a = 0; a < NAA; a++) {
                float aw = __ldg(&anchors[2 * a]);
                float ah = __ldg(&anchors[2 * a + 1]);
                float inter = fminf(gw, aw) * fminf(gh, ah);
                float un = gw * gh + aw * ah - inter;
                float r = __fdividef(inter, fmaxf(un, EPS12));
                if (r > best) { best = r; bn = a; awb = aw; ahb = ah; }
            }
            gi = (int)gx;
            gj = (int)gy;
            cell = bn * HW + gj * WWW + gi;
            s_cellAll[tid] = cell;

            // y-window filter for THIS band (IoU>0.6 ⇒ |py-gy| < 0.4*gh)
            float gl = gx - 0.5f * gw, gr = gx + 0.5f * gw;
            float gtp = gy - 0.5f * gh, gbt = gy + 0.5f * gh;
            float ylo = 0.9f * gtp + 0.1f * gbt;
            float yhi = 0.1f * gtp + 0.9f * gbt;
            if ((float)h0 < yhi + 0.01f && (float)(h0 + RB) > ylo - 0.01f) {
                int pos = atomicAdd(&s_m, 1);
                GTH g2;
                g2.gl = __floats2half2_rn(gl,  gl);
                g2.gr = __floats2half2_rn(gr,  gr);
                g2.gt = __floats2half2_rn(gtp, gtp);
                g2.gb = __floats2half2_rn(gbt, gbt);
                s_gh[pos]   = g2;
                s_gcn2[pos] = __floats2half2_rn(-0.375f * gw * gh,
                                                -0.375f * gw * gh);
            }
        }
        __syncthreads();

        // ---- winner resolution (last writer wins); exactly-once globals by
        //      the band block that owns the winner's row ----
        if (tid < ng) {
            bool win = true;
            for (int t2 = tid + 1; t2 < ng; t2++)
                if (s_cellAll[t2] == cell) win = false;

            if (win && (gj / RB) == band) {
                atomicAdd(&g_cnt[b * A4 + cell], 1);
                atomicAdd(&g_tsum[b * A4 + cell], ct);

                const float* ob = out + ((size_t)nb * CHN + bn * 6) * HW
                                      + gj * WWW + gi;
                float px = fsigm(ob[0])    + (float)gi;
                float py = fsigm(ob[HW])   + (float)gj;
                float pw = __expf(ob[2 * HW]) * awb;
                float ph = __expf(ob[3 * HW]) * ahb;

                float l  = fmaxf(gx - 0.5f * gw, px - 0.5f * pw);
                float r2 = fminf(gx + 0.5f * gw, px + 0.5f * pw);
                float tp = fmaxf(gy - 0.5f * gh, py - 0.5f * ph);
                float bt = fminf(gy + 0.5f * gh, py + 0.5f * ph);
                float inter = fmaxf(r2 - l, 0.0f) * fmaxf(bt - tp, 0.0f);
                float un = gw * gh + pw * ph - inter;
                float iou = __fdividef(inter, fmaxf(un, EPS12));

                int slot = atomicAdd(&s_nasg, 1);
                s_cell[slot] = cell;
                s_val[slot][0] = gx - (float)gi;
                s_val[slot][1] = gy - (float)gj;
                s_val[slot][2] = __logf(__fdividef(fmaxf(gw, EPS12), awb));
                s_val[slot][3] = __logf(__fdividef(fmaxf(gh, EPS12), ahb));
                s_val[slot][4] = iou;
                atomicOr(&s_bits[cell >> 5], 1u << (cell & 31));
            }
        }
        __syncthreads();

        // publish this block's g_cnt/g_tsum contribution for cls blocks
        if (tid == 0) {
            __threadfence();
            atomicAdd(&g_bdone[b], 1u);
        }

        int m = s_m, nasg = s_nasg;
        int mp = ((m + 4) / 5) * 5;
        for (int i = tid; i < mp; i += TPB) {
            if (i >= m) {
                GTH z; z.gl = z.gr = z.gt = z.gb = __floats2half2_rn(0.f, 0.f);
                s_gh[i]   = z;
                s_gcn2[i] = __floats2half2_rn(-1e30f, -1e30f);  // inert pad
            }
        }
        __syncthreads();

        // ---- per-cell fp32 loss pre-compute; pack boxes into half2 ----
        float plf[4], prf[4], ptf[4], pbf[4], k1f[4], dcv[4];
        float contrib = 0.0f;
#pragma unroll
        for (int i = 0; i < 4; i++) {
            int c = tid + i * TPB;
            int na = c / (RB * WWW);
            int rem = c - na * (RB * WWW);
            int r = rem / WWW;
            int ww = rem - r * WWW;
            int hh = h0 + r;
            bool live = (c < TILE) && (hh < HHH);
            if (live) {
                int hw = hh * WWW + ww;
                int idx = na * HW + hw;
                const float* ob = out + ((size_t)nb * CHN + na * 6) * HW + hw;
                float o0 = ob[0], o1 = ob[HW], o2 = ob[2 * HW],
                      o3 = ob[3 * HW], o4 = ob[4 * HW];

                float x = fsigm(o0), y = fsigm(o1), conf = fsigm(o4);
                float aw = __ldg(&anchors[2 * na]);
                float ah = __ldg(&anchors[2 * na + 1]);
                float px = x + (float)ww, py = y + (float)hh;
                float pw = __expf(o2) * aw, ph = __expf(o3) * ah;
                plf[i] = px - 0.5f * pw; prf[i] = px + 0.5f * pw;
                ptf[i] = py - 0.5f * ph; pbf[i] = py + 0.5f * ph;
                k1f[i] = 0.375f * pw * ph;

                float tx = 0.5f, ty = 0.5f, tw = 0.0f, th = 0.0f, tconf = 0.0f;
                if (s_bits[idx >> 5] & (1u << (idx & 31))) {
                    for (int k = 0; k < nasg; k++) {
                        if (s_cell[k] == idx) {
                            tx = s_val[k][0]; ty = s_val[k][1];
                            tw = s_val[k][2]; th = s_val[k][3];
                            tconf = s_val[k][4];
                            k1f[i] = 1e30f;   // assigned: conf term always on
                        }
                    }
                }
                // BCE(sigmoid(v),t) = softplus(v) - t*v; softplus = -log(1-sigm)
                float bxy = -__logf(1.0f - x) - tx * o0
                            -__logf(1.0f - y) - ty * o1;
                float dw = o2 - tw, dh = o3 - th;
                contrib += bxy + 0.5f * (dw * dw + dh * dh);
                dcv[i] = conf - tconf;
            } else {
                plf[i] = 100.f; prf[i] = -100.f;   // inert: relu(iw)=0, finite
                ptf[i] = 100.f; pbf[i] = -100.f;
                k1f[i] = 1e30f;
                dcv[i] = 0.0f;
            }
        }
        __half2 pl2[2], pr2[2], pt2[2], pb2[2], mm2[2];
#pragma unroll
        for (int p = 0; p < 2; p++) {
            pl2[p] = __floats2half2_rn(plf[2*p], plf[2*p+1]);
            pr2[p] = __floats2half2_rn(prf[2*p], prf[2*p+1]);
            pt2[p] = __floats2half2_rn(ptf[2*p], ptf[2*p+1]);
            pb2[p] = __floats2half2_rn(pbf[2*p], pbf[2*p+1]);
            mm2[p] = __floats2half2_rn(-1e30f, -1e30f);
        }
        const __half2 zero2 = __floats2half2_rn(0.f, 0.f);

        // ---- packed IoU>0.6 cull loop: 8 half2 ops per pair per gt ----
#pragma unroll 5
        for (int t = 0; t < mp; t++) {
            GTH g = s_gh[t];
            __half2 gcn = s_gcn2[t];
#pragma unroll
            for (int p = 0; p < 2; p++) {
                __half2 iw = __hsub2(__hmin2(pr2[p], g.gr), __hmax2(pl2[p], g.gl));
                __half2 ih = __hsub2(__hmin2(pb2[p], g.gb), __hmax2(pt2[p], g.gt));
                mm2[p] = __hmax2(mm2[p], __hfma2(__hmax2(iw, zero2), ih, gcn));
            }
        }

        // ---- epilogue: conf term ----
        float2 m0 = __half22float2(mm2[0]);
        float2 m1 = __half22float2(mm2[1]);
        float mmf[4] = {m0.x, m0.y, m1.x, m1.y};
#pragma unroll
        for (int i = 0; i < 4; i++) {
            float dc = (mmf[i] > k1f[i]) ? 0.0f : dcv[i];
            contrib += 0.5f * dc * dc;
        }

#pragma unroll
        for (int o = 16; o > 0; o >>= 1)
            contrib += __shfl_down_sync(0xffffffffu, contrib, o);
        __shared__ float s_red[3];
        if ((tid & 31) == 0) s_red[tid >> 5] = contrib;
        __syncthreads();
        if (tid == 0)
            atomicAdd(&g_accf[0], s_red[0] + s_red[1] + s_red[2]);
    } else {
        // ---- class-loss blocks: wait for their batch's mains, then NLL ----
        int base = (blockIdx.x - MAIN_BLOCKS) * TPB;
        int idx  = base + tid;
        int b0 = base / A4;
        int b1 = (base + TPB - 1) / A4;
        if (b1 >= BB) b1 = BB - 1;
        if (tid == 0) {
            volatile unsigned int* bd = g_bdone;
            while (bd[b0] < DONE_PER_B) __nanosleep(200);
            if (b1 != b0)
                while (bd[b1] < DONE_PER_B) __nanosleep(200);
        }
        __syncthreads();
        __threadfence();

        float nll = 0.0f, ns = 0.0f;
        if (idx < CLS_N) {
            int cnt = g_cnt[idx];
            if (cnt != 0) {
                float tsum = g_tsum[idx];
                g_cnt[idx] = 0;           // self-clean for next replay
                g_tsum[idx] = 0.0f;
                if (cnt == 1) {
                    int bb = idx / A4;
                    int a4 = idx - bb * A4;
                    int na = a4 / HW;
                    int hw = a4 - na * HW;
                    int label = (int)tsum;
                    size_t obase = ((size_t)bb * CC * CHN + na * 6 + 5) * HW + hw;
                    float mv = -1e30f, s = 0.0f, llab = 0.0f;
#pragma unroll
                    for (int c = 0; c < CC; c++) {
                        float l = out[obase + (size_t)c * CHN * HW];
                        if (c == label) llab = l;
                        if (l > mv) { s = s * __expf(mv - l) + 1.0f; mv = l; }
                        else        { s += __expf(l - mv); }
                    }
                    nll = mv + __logf(s) - llab;
                    ns  = 1.0f;
                }
            }
        }
#pragma unroll
        for (int o = 16; o > 0; o >>= 1) {
            nll += __shfl_down_sync(0xffffffffu, nll, o);
            ns  += __shfl_down_sync(0xffffffffu, ns,  o);
        }
        __shared__ float s_n[3], s_c[3];
        if ((tid & 31) == 0) { s_n[tid >> 5] = nll; s_c[tid >> 5] = ns; }
        __syncthreads();
        if (tid == 0) {
            float a = s_n[0] + s_n[1] + s_n[2];
            float bsum = s_c[0] + s_c[1] + s_c[2];
            if (a != 0.0f)    atomicAdd(&g_accf[1], a);
            if (bsum != 0.0f) atomicAdd(&g_accf[2], bsum);
        }
    }

    // ---- last-block final combine; resets ALL cross-replay state ----
    if (tid == 0) {
        __threadfence();
        unsigned int old = atomicAdd(&g_done, 1u);
        if (old == TOTB - 1) {
            float a0 = atomicExch(&g_accf[0], 0.0f);
            float a1 = atomicExch(&g_accf[1], 0.0f);
            float a2 = atomicExch(&g_accf[2], 0.0f);
            double N = (double)NBB * (double)A4;
            res[0] = (float)((double)a0 / N +
                             (double)a1 / fmax((double)a2, 1.0));
#pragma unroll
            for (int i = 0; i < BB; i++) g_bdone[i] = 0u;
            g_done = 0;
        }
    }
}

// ---------------------------------------------------------------------------
extern "C" void kernel_launch(void* const* d_in, const int* in_sizes, int n_in,
                              void* d_out, int out_size) {
    const float* out_t   = (const float*)d_in[0];
    const float* target  = (const float*)d_in[1];
    const float* anchors = (const float*)d_in[2];
    float* res = (float*)d_out;

    k_all<<<TOTB, TPB>>>(out_t, target, anchors, res);
}

// round 16
// speedup vs baseline: 1.1706x; 1.1706x over previous
#include <cuda_runtime.h>
#include <cuda_fp16.h>
#include <cstdint>

// Problem constants
#define BB     64
#define CC     20
#define NAA    5
#define HHH    19
#define WWW    19
#define HW     361      // 19*19
#define TT     50
#define NBB    1280     // B*C
#define A4     1805     // NA*H*W
#define CHN    30       // NA*(5+NCPA)
#define EPS12  1e-12f
#define RB     4                              // rows per band
#define BANDS  5
#define TILE   (NAA * RB * WWW)               // 380 cells per band-block
#define TPB    96                             // 3 warps; 4 cells/thread
#define MAIN_BLOCKS (NBB * BANDS)             // 6400
#define CLS_N   (BB * A4)                     // 115520
#define CLS_BLOCKS ((CLS_N + TPB - 1) / TPB)  // 1204
#define TOTB    (MAIN_BLOCKS + CLS_BLOCKS)

// Static scratch (no allocations; self-cleaning or overwritten every run)
struct alignas(16) GTH { __half2 gl, gr, gt, gb; };
__device__ int    g_bm[NBB][BANDS];           // gts per (nb, band)
__device__ GTH    g_bgh[NBB][BANDS][TT];      // gt box, broadcast half2
__device__ __half2 g_bgc2[NBB][BANDS][TT];    // -0.375*area, broadcast half2
__device__ int    g_bn[NBB][BANDS];           // assignments per (nb, band)
__device__ int    g_bcell[NBB][BANDS][TT];
__device__ float  g_bval[NBB][BANDS][TT][5];  // tx, ty, tw, th, tconf
__device__ int    g_cnt[CLS_N];               // winners per (b, a4) across C
__device__ float  g_tsum[CLS_N];
__device__ float  g_accf[3];                  // dense, cls nll, nsel
__device__ unsigned int g_done;

__device__ __forceinline__ float fsigm(float v) {
    return __fdividef(1.0f, 1.0f + __expf(-v));
}

// ---------------------------------------------------------------------------
// One block (64 threads) per nb row. Computes gt boxes (converted to
// broadcast half2), winner assignments, and per-band compacted lists.
__global__ void k_assign(const float* __restrict__ out,
                         const float* __restrict__ target,
                         const float* __restrict__ anchors) {
    int nb = blockIdx.x;
    int t  = threadIdx.x;

    __shared__ float s_tg[TT * 5];
    __shared__ int   s_ng;
    __shared__ int   s_bm[BANDS], s_bn[BANDS];
    __shared__ int   s_cell[TT];

    if (t == 0) s_ng = TT;
    if (t < BANDS) { s_bm[t] = 0; s_bn[t] = 0; }
    const float* tg = target + (size_t)nb * TT * 5;
    for (int i = t; i < TT * 5; i += 64) s_tg[i] = tg[i];
    __syncthreads();

    if (t < TT && s_tg[t * 5 + 1] == 0.0f) atomicMin(&s_ng, t);
    __syncthreads();
    int ng = s_ng;

    float gx = 0.f, gy = 0.f, gw = 0.f, gh = 0.f, ct = 0.f;
    int gi = 0, gj = 0, bn = 0, cell = -1;
    float awb = 1.f, ahb = 1.f;

    if (t < ng) {
        ct = s_tg[t * 5 + 0];
        gx = s_tg[t * 5 + 1] * (float)WWW;
        gy = s_tg[t * 5 + 2] * (float)HHH;
        gw = s_tg[t * 5 + 3] * (float)WWW;
        gh = s_tg[t * 5 + 4] * (float)HHH;

        float best = -1.0f;
#pragma unroll
        for (int a = 0; a < NAA; a++) {
            float aw = __ldg(&anchors[2 * a]);
            float ah = __ldg(&anchors[2 * a + 1]);
            float inter = fminf(gw, aw) * fminf(gh, ah);
            float un = gw * gh + aw * ah - inter;
            float r = __fdividef(inter, fmaxf(un, EPS12));
            if (r > best) { best = r; bn = a; awb = aw; ahb = ah; }
        }
        gi = (int)gx;
        gj = (int)gy;
        cell = bn * HW + gj * WWW + gi;   // anchor-major cell id
        s_cell[t] = cell;

        // per-band gt list: gt matters only for rows hh in (gy-0.4gh-1, gy+0.4gh)
        float gl = gx - 0.5f * gw, gr = gx + 0.5f * gw;
        float gtp = gy - 0.5f * gh, gbt = gy + 0.5f * gh;
        float ylo = 0.9f * gtp + 0.1f * gbt;  // gy - 0.4*gh
        float yhi = 0.1f * gtp + 0.9f * gbt;  // gy + 0.4*gh
        float gcn = -0.375f * gw * gh;
        GTH gh2;
        gh2.gl = __floats2half2_rn(gl,  gl);
        gh2.gr = __floats2half2_rn(gr,  gr);
        gh2.gt = __floats2half2_rn(gtp, gtp);
        gh2.gb = __floats2half2_rn(gbt, gbt);
        __half2 gcn2 = __floats2half2_rn(gcn, gcn);
#pragma unroll
        for (int bd = 0; bd < BANDS; bd++) {
            float h0 = (float)(bd * RB);
            if (h0 < yhi + 0.01f && h0 + (float)RB > ylo - 0.01f) {
                int pos = atomicAdd(&s_bm[bd], 1);
                g_bgh[nb][bd][pos]  = gh2;
                g_bgc2[nb][bd][pos] = gcn2;
            }
        }
    }
    __syncthreads();

    if (t < ng) {
        // last writer wins for this cell within this nb row
        bool win = true;
        for (int t2 = t + 1; t2 < ng; t2++)
            if (s_cell[t2] == cell) win = false;

        if (win) {
            int b = nb / CC;
            atomicAdd(&g_cnt[b * A4 + cell], 1);
            atomicAdd(&g_tsum[b * A4 + cell], ct);

            const float* ob = out + ((size_t)nb * CHN + bn * 6) * HW + gj * WWW + gi;
            float px = fsigm(ob[0])    + (float)gi;
            float py = fsigm(ob[HW])   + (float)gj;
            float pw = __expf(ob[2 * HW]) * awb;
            float ph = __expf(ob[3 * HW]) * ahb;

            float l  = fmaxf(gx - 0.5f * gw, px - 0.5f * pw);
            float r2 = fminf(gx + 0.5f * gw, px + 0.5f * pw);
            float tp = fmaxf(gy - 0.5f * gh, py - 0.5f * ph);
            float bt = fminf(gy + 0.5f * gh, py + 0.5f * ph);
            float inter = fmaxf(r2 - l, 0.0f) * fmaxf(bt - tp, 0.0f);
            float un = gw * gh + pw * ph - inter;
            float iou = __fdividef(inter, fmaxf(un, EPS12));

            int bd = gj / RB;
            int slot = atomicAdd(&s_bn[bd], 1);
            g_bcell[nb][bd][slot] = cell;
            g_bval[nb][bd][slot][0] = gx - (float)gi;
            g_bval[nb][bd][slot][1] = gy - (float)gj;
            g_bval[nb][bd][slot][2] = __logf(__fdividef(fmaxf(gw, EPS12), awb));
            g_bval[nb][bd][slot][3] = __logf(__fdividef(fmaxf(gh, EPS12), ahb));
            g_bval[nb][bd][slot][4] = iou;
        }
    }
    __syncthreads();
    if (t < BANDS) {
        g_bm[nb][t] = s_bm[t];
        g_bn[nb][t] = s_bn[t];
    }
}

// ---------------------------------------------------------------------------
// Fused dense losses: 96 threads, 4 cells/thread fully packed as 2x half2
// lanes (boxes, k1, dcv) for the IoU cull loop + epilogue. Dense loss fp32.
// (96, 11): 59-reg kernel fits the 62-reg cap -> occ ceiling 45.8%, no spill.
__global__ void __launch_bounds__(TPB, 11)
k_fused(const float* __restrict__ out,
        const float* __restrict__ anchors,
        float* __restrict__ res) {
    int tid = threadIdx.x;

    if (blockIdx.x < MAIN_BLOCKS) {
        int nb   = blockIdx.x / BANDS;
        int band = blockIdx.x - nb * BANDS;
        int h0   = band * RB;

        // ---- shared tables (precompacted per band) ----
        __shared__ GTH     s_gh[TT];
        __shared__ __half2 s_gcn2[TT];
        __shared__ int     s_cell[TT];
        __shared__ float   s_val[TT][5];
        __shared__ uint32_t s_bits[57];

        int m    = g_bm[nb][band];
        int nasg = g_bn[nb][band];
        int mp   = ((m + 4) / 5) * 5;

        if (tid < 57) s_bits[tid] = 0u;
        for (int i = tid; i < mp; i += TPB) {
            if (i < m) {
                s_gh[i]   = g_bgh[nb][band][i];
                s_gcn2[i] = g_bgc2[nb][band][i];
            } else {
                GTH z; z.gl = z.gr = z.gt = z.gb = __floats2half2_rn(0.f, 0.f);
                s_gh[i]   = z;
                s_gcn2[i] = __floats2half2_rn(-1e30f, -1e30f);  // -inf: inert
            }
        }
        for (int i = tid; i < nasg * 5; i += TPB)
            (&s_val[0][0])[i] = (&g_bval[nb][band][0][0])[i];
        __syncthreads();
        for (int i = tid; i < nasg; i += TPB) {
            int c = g_bcell[nb][band][i];
            s_cell[i] = c;
            atomicOr(&s_bits[c >> 5], 1u << (c & 31));
        }
        __syncthreads();

        // ---- per-cell fp32 loss pre-compute; pack everything into half2 ----
        float plf[4], prf[4], ptf[4], pbf[4], k1f[4], dcvf[4];
        float contrib = 0.0f;
#pragma unroll
        for (int i = 0; i < 4; i++) {
            int c = tid + i * TPB;
            int na = c / (RB * WWW);
            int rem = c - na * (RB * WWW);
            int r = rem / WWW;
            int ww = rem - r * WWW;
            int hh = h0 + r;
            bool live = (c < TILE) && (hh < HHH);
            if (live) {
                int hw = hh * WWW + ww;
                int idx = na * HW + hw;
                const float* ob = out + ((size_t)nb * CHN + na * 6) * HW + hw;
                float o0 = ob[0], o1 = ob[HW], o2 = ob[2 * HW],
                      o3 = ob[3 * HW], o4 = ob[4 * HW];

                float x = fsigm(o0), y = fsigm(o1), conf = fsigm(o4);
                float aw = __ldg(&anchors[2 * na]);
                float ah = __ldg(&anchors[2 * na + 1]);
                float px = x + (float)ww, py = y + (float)hh;
                float pw = __expf(o2) * aw, ph = __expf(o3) * ah;
                plf[i] = px - 0.5f * pw; prf[i] = px + 0.5f * pw;
                ptf[i] = py - 0.5f * ph; pbf[i] = py + 0.5f * ph;
                k1f[i] = 0.375f * pw * ph;

                float tx = 0.5f, ty = 0.5f, tw = 0.0f, th = 0.0f, tconf = 0.0f;
                if (s_bits[idx >> 5] & (1u << (idx & 31))) {
                    for (int k = 0; k < nasg; k++) {
                        if (s_cell[k] == idx) {
                            tx = s_val[k][0]; ty = s_val[k][1];
                            tw = s_val[k][2]; th = s_val[k][3];
                            tconf = s_val[k][4];
                            k1f[i] = 1e30f;   // -> +inf in half: conf always on
                        }
                    }
                }
                // BCE(sigmoid(v),t) = softplus(v) - t*v; softplus = -log(1-sigm)
                float bxy = -__logf(1.0f - x) - tx * o0
                            -__logf(1.0f - y) - ty * o1;
                float dw = o2 - tw, dh = o3 - th;
                contrib += bxy + 0.5f * (dw * dw + dh * dh);
                dcvf[i] = conf - tconf;
            } else {
                plf[i] = 100.f; prf[i] = -100.f;   // inert: relu(iw)=0, finite
                ptf[i] = 100.f; pbf[i] = -100.f;
                k1f[i] = 1e30f;
                dcvf[i] = 0.0f;
            }
        }
        __half2 pl2[2], pr2[2], pt2[2], pb2[2], mm2[2], k12[2], dcv2[2];
#pragma unroll
        for (int p = 0; p < 2; p++) {
            pl2[p]  = __floats2half2_rn(plf[2*p],  plf[2*p+1]);
            pr2[p]  = __floats2half2_rn(prf[2*p],  prf[2*p+1]);
            pt2[p]  = __floats2half2_rn(ptf[2*p],  ptf[2*p+1]);
            pb2[p]  = __floats2half2_rn(pbf[2*p],  pbf[2*p+1]);
            k12[p]  = __floats2half2_rn(k1f[2*p],  k1f[2*p+1]);
            dcv2[p] = __floats2half2_rn(dcvf[2*p], dcvf[2*p+1]);
            mm2[p]  = __floats2half2_rn(-1e30f, -1e30f);
        }
        const __half2 zero2 = __floats2half2_rn(0.f, 0.f);

        // ---- packed IoU>0.6 cull loop: 8 half2 ops per pair per gt ----
#pragma unroll 5
        for (int t = 0; t < mp; t++) {
            GTH g = s_gh[t];
            __half2 gcn = s_gcn2[t];
#pragma unroll
            for (int p = 0; p < 2; p++) {
                __half2 iw = __hsub2(__hmin2(pr2[p], g.gr), __hmax2(pl2[p], g.gl));
                __half2 ih = __hsub2(__hmin2(pb2[p], g.gb), __hmax2(pt2[p], g.gt));
                mm2[p] = __hmax2(mm2[p], __hfma2(__hmax2(iw, zero2), ih, gcn));
            }
        }

        // ---- packed epilogue: conf term (keep lane iff mm <= k1) ----
#pragma unroll
        for (int p = 0; p < 2; p++) {
            __half2 keep = __hle2(mm2[p], k12[p]);   // 1.0 where NOT over
            __half2 dc   = __hmul2(dcv2[p], keep);
            float2 f = __half22float2(__hmul2(dc, dc));
            contrib += 0.5f * (f.x + f.y);
        }

#pragma unroll
        for (int o = 16; o > 0; o >>= 1)
            contrib += __shfl_down_sync(0xffffffffu, contrib, o);
        __shared__ float s_red[3];
        if ((tid & 31) == 0) s_red[tid >> 5] = contrib;
        __syncthreads();
        if (tid == 0)
            atomicAdd(&g_accf[0], s_red[0] + s_red[1] + s_red[2]);
    } else {
        // ---- class-loss blocks (self-cleaning: reset g_cnt/g_tsum) ----
        int idx = (blockIdx.x - MAIN_BLOCKS) * TPB + tid;
        float nll = 0.0f, ns = 0.0f;
        if (idx < CLS_N) {
            int cnt = g_cnt[idx];
            if (cnt != 0) {
                float tsum = g_tsum[idx];
                g_cnt[idx] = 0;
                g_tsum[idx] = 0.0f;
                if (cnt == 1) {
                    int b  = idx / A4;
                    int a4 = idx - b * A4;
                    int na = a4 / HW;
                    int hw = a4 - na * HW;
                    int label = (int)tsum;
                    size_t obase = ((size_t)b * CC * CHN + na * 6 + 5) * HW + hw;
                    float mv = -1e30f, s = 0.0f, llab = 0.0f;
#pragma unroll
                    for (int c = 0; c < CC; c++) {
                        float l = out[obase + (size_t)c * CHN * HW];
                        if (c == label) llab = l;
                        if (l > mv) { s = s * __expf(mv - l) + 1.0f; mv = l; }
                        else        { s += __expf(l - mv); }
                    }
                    nll = mv + __logf(s) - llab;
                    ns  = 1.0f;
                }
            }
        }
#pragma unroll
        for (int o = 16; o > 0; o >>= 1) {
            nll += __shfl_down_sync(0xffffffffu, nll, o);
            ns  += __shfl_down_sync(0xffffffffu, ns,  o);
        }
        __shared__ float s_n[3], s_c[3];
        if ((tid & 31) == 0) { s_n[tid >> 5] = nll; s_c[tid >> 5] = ns; }
        __syncthreads();
        if (tid == 0) {
            float a = s_n[0] + s_n[1] + s_n[2];
            float bsum = s_c[0] + s_c[1] + s_c[2];
            if (a != 0.0f)    atomicAdd(&g_accf[1], a);
            if (bsum != 0.0f) atomicAdd(&g_accf[2], bsum);
        }
    }

    // ---- last-block final combine (also resets g_accf for next replay) ----
    if (tid == 0) {
        __threadfence();
        unsigned int old = atomicAdd(&g_done, 1u);
        if (old == TOTB - 1) {
            float a0 = atomicExch(&g_accf[0], 0.0f);
            float a1 = atomicExch(&g_accf[1], 0.0f);
            float a2 = atomicExch(&g_accf[2], 0.0f);
            double N = (double)NBB * (double)A4;
            res[0] = (float)((double)a0 / N +
                             (double)a1 / fmax((double)a2, 1.0));
            g_done = 0;
        }
    }
}

// ---------------------------------------------------------------------------
extern "C" void kernel_launch(void* const* d_in, const int* in_sizes, int n_in,
                              void* d_out, int out_size) {
    const float* out_t   = (const float*)d_in[0];
    const float* target  = (const float*)d_in[1];
    const float* anchors = (const float*)d_in[2];
    float* res = (float*)d_out;

    k_assign<<<NBB, 64>>>(out_t, target, anchors);
    k_fused<<<TOTB, TPB>>>(out_t, anchors, res);
}